// round 5
// baseline (speedup 1.0000x reference)
#include <cuda_runtime.h>
#include <cuda_bf16.h>
#include <math.h>

#define BB 64
#define SS 64
#define HH 1024
#define TT 40
#define VV 32000

// ---------------- scratch (device globals; no allocation allowed) ----------
__device__ float g_keysU[BB * SS * HH];                  // 16.8 MB fp32
__device__ float g_h[BB * HH];
__device__ float g_logits[BB * VV];                      // 8.2 MB
__device__ float g_qpart[4][BB * HH];                    // split-K partials
__device__ float g_gipart[4][BB * 3 * HH];
__device__ float g_ghpart[4][BB * 3 * HH];
__device__ __nv_bfloat16 g_wout16[(long)VV * HH];        // 65.5 MB
__device__ __nv_bfloat16 g_eo3[(long)BB * SS * 3 * HH];  // 25.2 MB  [hi,hi,lo]
__device__ __nv_bfloat16 g_ua3[(long)HH * 3 * HH];       // [hi,lo,hi]
__device__ __nv_bfloat16 g_wa3[(long)HH * 3 * HH];
__device__ __nv_bfloat16 g_wih3[(long)3 * HH * 3 * 2 * HH];  // 37.7 MB
__device__ __nv_bfloat16 g_whh3[(long)3 * HH * 3 * HH];
__device__ __nv_bfloat16 g_h3[BB * 3 * HH];              // [hi,hi,lo]
__device__ __nv_bfloat16 g_x3[BB * 3 * 2 * HH];          // [hi,hi,lo] of [emb,ctx]

// ---------------------------------------------------------------------------
// helpers
// ---------------------------------------------------------------------------
__device__ __forceinline__ float fast_tanh(float x) {
    float y;
    asm("tanh.approx.f32 %0, %1;" : "=f"(y) : "f"(x));
    return y;
}
__device__ __forceinline__ unsigned sptr(const void* p) {
    return (unsigned)__cvta_generic_to_shared(p);
}
__device__ __forceinline__ void cpa16(unsigned dst, const void* src) {
    asm volatile("cp.async.cg.shared.global [%0], [%1], 16;" :: "r"(dst), "l"(src));
}
__device__ __forceinline__ void ldm4(unsigned* r, unsigned addr) {
    asm volatile("ldmatrix.sync.aligned.m8n8.x4.shared.b16 {%0,%1,%2,%3}, [%4];"
                 : "=r"(r[0]), "=r"(r[1]), "=r"(r[2]), "=r"(r[3]) : "r"(addr));
}
__device__ __forceinline__ void mma_bf16(float* d, const unsigned* a,
                                         unsigned b0, unsigned b1) {
    asm volatile(
        "mma.sync.aligned.m16n8k16.row.col.f32.bf16.bf16.f32 "
        "{%0,%1,%2,%3}, {%4,%5,%6,%7}, {%8,%9}, {%0,%1,%2,%3};"
        : "+f"(d[0]), "+f"(d[1]), "+f"(d[2]), "+f"(d[3])
        : "r"(a[0]), "r"(a[1]), "r"(a[2]), "r"(a[3]), "r"(b0), "r"(b1));
}

// ---------------------------------------------------------------------------
// fp32 -> bf16 plain (4 elems/thread) — for W_out
// ---------------------------------------------------------------------------
__global__ void conv_bf16(const float* __restrict__ s, __nv_bfloat16* __restrict__ d)
{
    long i = ((long)blockIdx.x * 256 + threadIdx.x) * 4;
    float4 v = *(const float4*)(s + i);
    __nv_bfloat162* dp = (__nv_bfloat162*)(d + i);
    dp[0] = __floats2bfloat162_rn(v.x, v.y);
    dp[1] = __floats2bfloat162_rn(v.z, v.w);
}

// ---------------------------------------------------------------------------
// fp32 [R,K] -> bf16x3 [R,3K].  isA=1: [hi,hi,lo] (activation side)
//                                isA=0: [hi,lo,hi] (weight side)
// ---------------------------------------------------------------------------
__global__ void split3(const float* __restrict__ in, __nv_bfloat16* __restrict__ out,
                       int K, int isA)
{
    long idx = (long)blockIdx.x * 256 + threadIdx.x;
    long r = idx / K;
    int k = (int)(idx - r * K);
    float v = in[idx];
    __nv_bfloat16 hi = __float2bfloat16(v);
    __nv_bfloat16 lo = __float2bfloat16(v - __bfloat162float(hi));
    long o = r * 3 * K + k;
    out[o] = hi;
    out[o + K] = isA ? hi : lo;
    out[o + 2 * K] = isA ? lo : hi;
}

// ---------------------------------------------------------------------------
// bf16 tensor-core GEMM: C[M,N] = A[M,K'] @ B[N,K']^T (+ bias)
// Block tile 64(M) x 128(N), K-chunk 64, 8 warps, m16n8k16 HMMA,
// cp.async double-buffered xor-swizzled smem.
// grid = (N/128, M/64, splitZ). Each z-slice covers kcPer chunks starting at
// z*kcPer and stores (biasless) into C + z*strideZ; bias path when gridDim.z==1.
// ---------------------------------------------------------------------------
__global__ void gemm_mma(const __nv_bfloat16* __restrict__ A,
                         const __nv_bfloat16* __restrict__ Bw,
                         const float* __restrict__ bias,
                         float* __restrict__ C,
                         int kcPer, int lda, int ldb, int N, long strideZ)
{
    __shared__ __align__(1024) unsigned char smem_raw[49152];
    const unsigned sb0 = sptr(smem_raw);
    const int tid = threadIdx.x;
    const int wid = tid >> 5, lane = tid & 31;
    const int warp_m = wid >> 2;
    const int warp_n = wid & 3;
    const int n0 = blockIdx.x * 128;
    const int m0 = blockIdx.y * 64;
    const int kcBegin = blockIdx.z * kcPer;

    float acc[2][4][4];
#pragma unroll
    for (int a = 0; a < 2; a++)
#pragma unroll
        for (int b = 0; b < 4; b++)
#pragma unroll
            for (int c = 0; c < 4; c++) acc[a][b][c] = 0.f;

    auto stage = [&](unsigned sbase, int kc) {
#pragma unroll
        for (int i = 0; i < 6; i++) {
            int idx = tid + i * 256;
            if (idx < 512) {
                int r = idx >> 3, c = idx & 7;
                unsigned dst = sbase + (unsigned)(((r << 3) + (c ^ (r & 7))) << 4);
                cpa16(dst, A + (long)(m0 + r) * lda + kc * 64 + c * 8);
            } else {
                int j = idx - 512;
                int r = j >> 3, c = j & 7;
                unsigned dst = sbase + 8192u + (unsigned)(((r << 3) + (c ^ (r & 7))) << 4);
                cpa16(dst, Bw + (long)(n0 + r) * ldb + kc * 64 + c * 8);
            }
        }
    };

    stage(sb0, kcBegin);
    asm volatile("cp.async.commit_group;");

    for (int i = 0; i < kcPer; i++) {
        if (i + 1 < kcPer) stage(sb0 + ((i + 1) & 1) * 24576u, kcBegin + i + 1);
        asm volatile("cp.async.commit_group;");
        asm volatile("cp.async.wait_group 1;");
        __syncthreads();

        const unsigned bA = sb0 + (i & 1) * 24576u;
        const unsigned bB = bA + 8192u;

#pragma unroll
        for (int kk = 0; kk < 4; kk++) {
            unsigned afr[2][4], bfr[2][4];
#pragma unroll
            for (int mt = 0; mt < 2; mt++) {
                int r = warp_m * 32 + mt * 16 + (lane & 15);
                int c = 2 * kk + (lane >> 4);
                ldm4(afr[mt], bA + (unsigned)(((r << 3) + (c ^ (r & 7))) << 4));
            }
#pragma unroll
            for (int np = 0; np < 2; np++) {
                int r = warp_n * 32 + np * 16 + ((lane >> 4) << 3) + (lane & 7);
                int c = 2 * kk + ((lane >> 3) & 1);
                ldm4(bfr[np], bB + (unsigned)(((r << 3) + (c ^ (r & 7))) << 4));
            }
#pragma unroll
            for (int mt = 0; mt < 2; mt++)
#pragma unroll
                for (int nt = 0; nt < 4; nt++)
                    mma_bf16(acc[mt][nt], afr[mt],
                             bfr[nt >> 1][(nt & 1) * 2], bfr[nt >> 1][(nt & 1) * 2 + 1]);
        }
        __syncthreads();
    }

    float* Cz = C + (long)blockIdx.z * strideZ;
#pragma unroll
    for (int mt = 0; mt < 2; mt++) {
        int row = m0 + warp_m * 32 + mt * 16 + (lane >> 2);
#pragma unroll
        for (int nt = 0; nt < 4; nt++) {
            int col = n0 + warp_n * 32 + nt * 8 + ((lane & 3) << 1);
            float* cp = Cz + (long)row * N + col;
            float b0 = 0.f, b1 = 0.f;
            if (bias) { b0 = bias[col]; b1 = bias[col + 1]; }
            float2 v0 = {acc[mt][nt][0] + b0, acc[mt][nt][1] + b1};
            float2 v1 = {acc[mt][nt][2] + b0, acc[mt][nt][3] + b1};
            *(float2*)cp = v0;
            *(float2*)(cp + (long)8 * N) = v1;
        }
    }
}

// ---------------------------------------------------------------------------
// h0 -> g_h (fp32) and g_h3 (bf16x3 activation layout)
// ---------------------------------------------------------------------------
__global__ void copy_h0(const float* __restrict__ h0)
{
    int i = blockIdx.x * 256 + threadIdx.x;
    float v = h0[i];
    g_h[i] = v;
    int r = i >> 10, k = i & 1023;
    __nv_bfloat16 hi = __float2bfloat16(v);
    __nv_bfloat16 lo = __float2bfloat16(v - __bfloat162float(hi));
    g_h3[r * 3072 + k] = hi;
    g_h3[r * 3072 + 1024 + k] = hi;
    g_h3[r * 3072 + 2048 + k] = lo;
}

__global__ void write_hidden(float* __restrict__ out_hid)
{
    int i = blockIdx.x * 256 + threadIdx.x;
    out_hid[i] = g_h[i];
}

// ---------------------------------------------------------------------------
// Fused attention: one block per batch b (256 threads).
// q = sum of 4 split-K partials + ba; scores = Va.tanh(q+keysU)+bv;
// softmax; attn output; ctx; x3 = bf16x3([emb_tok, ctx]).
// ---------------------------------------------------------------------------
__global__ void attn_fused(const float* __restrict__ EO,
                           const float* __restrict__ Va,
                           const float* __restrict__ bv,
                           const float* __restrict__ ba,
                           const float* __restrict__ emb,
                           const int* __restrict__ target,
                           float* __restrict__ out_attn, int t)
{
    __shared__ float qs[HH];
    __shared__ float vs[HH];
    __shared__ float sc[SS];
    __shared__ float w[SS];
    const int b = blockIdx.x;
    const int tid = threadIdx.x;
    const int warp = tid >> 5, lane = tid & 31;

    for (int i = tid; i < HH; i += 256) {
        qs[i] = g_qpart[0][b * HH + i] + g_qpart[1][b * HH + i] +
                g_qpart[2][b * HH + i] + g_qpart[3][b * HH + i] + ba[i];
        vs[i] = Va[i];
    }
    __syncthreads();

    for (int s = warp; s < SS; s += 8) {
        const float* kp = &g_keysU[((long)(b * SS + s)) * HH];
        float sum = 0.f;
        for (int h = lane; h < HH; h += 32)
            sum += fast_tanh(qs[h] + kp[h]) * vs[h];
#pragma unroll
        for (int o = 16; o; o >>= 1) sum += __shfl_xor_sync(~0u, sum, o);
        if (!lane) sc[s] = sum + bv[0];
    }
    __syncthreads();

    if (warp == 0) {
        float v0 = sc[lane], v1 = sc[lane + 32];
        float mx = fmaxf(v0, v1);
#pragma unroll
        for (int o = 16; o; o >>= 1) mx = fmaxf(mx, __shfl_xor_sync(~0u, mx, o));
        float e0 = expf(v0 - mx), e1 = expf(v1 - mx);
        float sm = e0 + e1;
#pragma unroll
        for (int o = 16; o; o >>= 1) sm += __shfl_xor_sync(~0u, sm, o);
        float inv = 1.f / sm;
        w[lane] = e0 * inv;
        w[lane + 32] = e1 * inv;
        out_attn[((long)(b * TT + t)) * SS + lane] = e0 * inv;
        out_attn[((long)(b * TT + t)) * SS + lane + 32] = e1 * inv;
    }
    __syncthreads();

    const int tok = (t == 0) ? 0 : target[b * TT + t - 1];  // SOS_INDEX = 0
    __nv_bfloat16* xr = &g_x3[b * 6144];

    for (int h = tid; h < HH; h += 256) {
        // ctx half (cols HH..2HH of x)
        float acc = 0.f;
        const float* ep = &EO[(long)b * SS * HH + h];
#pragma unroll 8
        for (int s = 0; s < SS; s++) acc += w[s] * ep[(long)s * HH];
        __nv_bfloat16 chi = __float2bfloat16(acc);
        __nv_bfloat16 clo = __float2bfloat16(acc - __bfloat162float(chi));
        xr[1024 + h] = chi;
        xr[2048 + 1024 + h] = chi;
        xr[4096 + 1024 + h] = clo;
        // embedding half (cols 0..HH of x)
        float e = emb[(long)tok * HH + h];
        __nv_bfloat16 ehi = __float2bfloat16(e);
        __nv_bfloat16 elo = __float2bfloat16(e - __bfloat162float(ehi));
        xr[h] = ehi;
        xr[2048 + h] = ehi;
        xr[4096 + h] = elo;
    }
}

// ---------------------------------------------------------------------------
// GRU pointwise: sums gi/gh split-K partials + biases, updates g_h and g_h3
// ---------------------------------------------------------------------------
__global__ void gru_step(const float* __restrict__ b_ih, const float* __restrict__ b_hh)
{
    const int b = blockIdx.x;
    for (int j = threadIdx.x; j < HH; j += 256) {
        const int base = b * 3 * HH;
        float ir = 0, iz = 0, in = 0, hr = 0, hz = 0, hn = 0;
#pragma unroll
        for (int z = 0; z < 4; z++) {
            ir += g_gipart[z][base + j];
            iz += g_gipart[z][base + HH + j];
            in += g_gipart[z][base + 2 * HH + j];
            hr += g_ghpart[z][base + j];
            hz += g_ghpart[z][base + HH + j];
            hn += g_ghpart[z][base + 2 * HH + j];
        }
        ir += b_ih[j]; iz += b_ih[HH + j]; in += b_ih[2 * HH + j];
        hr += b_hh[j]; hz += b_hh[HH + j]; hn += b_hh[2 * HH + j];
        float r = 1.f / (1.f + expf(-(ir + hr)));
        float z = 1.f / (1.f + expf(-(iz + hz)));
        float n = tanhf(in + r * hn);
        float ho = g_h[b * HH + j];
        float out = (1.f - z) * n + z * ho;
        g_h[b * HH + j] = out;
        __nv_bfloat16 hi = __float2bfloat16(out);
        __nv_bfloat16 lo = __float2bfloat16(out - __bfloat162float(hi));
        g_h3[b * 3072 + j] = hi;
        g_h3[b * 3072 + 1024 + j] = hi;
        g_h3[b * 3072 + 2048 + j] = lo;
    }
}

// ---------------------------------------------------------------------------
// log_softmax over V per batch row
// ---------------------------------------------------------------------------
__global__ void logsoftmax_step(float* __restrict__ out_dec, int t)
{
    __shared__ float red[512];
    const int b = blockIdx.x;
    const int tid = threadIdx.x;
    const float* lg = &g_logits[(long)b * VV];

    float mx = -1e30f;
    for (int v = tid; v < VV; v += 512) mx = fmaxf(mx, lg[v]);
    red[tid] = mx; __syncthreads();
    for (int s = 256; s; s >>= 1) {
        if (tid < s) red[tid] = fmaxf(red[tid], red[tid + s]);
        __syncthreads();
    }
    mx = red[0];
    __syncthreads();

    float sum = 0.f;
    for (int v = tid; v < VV; v += 512) sum += expf(lg[v] - mx);
    red[tid] = sum; __syncthreads();
    for (int s = 256; s; s >>= 1) {
        if (tid < s) red[tid] += red[tid + s];
        __syncthreads();
    }
    const float lse = mx + logf(red[0]);

    float* op = &out_dec[((long)(b * TT + t)) * VV];
    for (int v = tid; v < VV; v += 512) op[v] = lg[v] - lse;
}

// ---------------------------------------------------------------------------
extern "C" void kernel_launch(void* const* d_in, const int* in_sizes, int n_in,
                              void* d_out, int out_size)
{
    const float* EO     = (const float*)d_in[0];   // [B,S,H]
    const float* h0     = (const float*)d_in[1];   // [B,H]
    const int*   target = (const int*)  d_in[2];   // [B,T]
    const float* emb    = (const float*)d_in[3];   // [V,H]
    const float* Wa     = (const float*)d_in[4];   // [H,H]
    const float* ba     = (const float*)d_in[5];
    const float* Ua     = (const float*)d_in[6];   // [H,H]
    const float* bu     = (const float*)d_in[7];
    const float* Va     = (const float*)d_in[8];   // [1,H]
    const float* bvp    = (const float*)d_in[9];
    const float* W_ih   = (const float*)d_in[10];  // [3H,2H]
    const float* W_hh   = (const float*)d_in[11];  // [3H,H]
    const float* b_ih   = (const float*)d_in[12];
    const float* b_hh   = (const float*)d_in[13];
    const float* W_out  = (const float*)d_in[14];  // [V,H]
    const float* b_out  = (const float*)d_in[15];

    float* out      = (float*)d_out;
    float* out_dec  = out;                          // [B,T,V]
    float* out_hid  = out + (long)BB * TT * VV;     // [1,B,H]
    float* out_attn = out_hid + (long)BB * HH;      // [B,T,S]

    float *p_keysU, *p_logits, *p_qpart, *p_gipart, *p_ghpart;
    __nv_bfloat16 *p_wout16, *p_eo3, *p_ua3, *p_wa3, *p_wih3, *p_whh3, *p_h3, *p_x3;
    cudaGetSymbolAddress((void**)&p_keysU,  g_keysU);
    cudaGetSymbolAddress((void**)&p_logits, g_logits);
    cudaGetSymbolAddress((void**)&p_qpart,  g_qpart);
    cudaGetSymbolAddress((void**)&p_gipart, g_gipart);
    cudaGetSymbolAddress((void**)&p_ghpart, g_ghpart);
    cudaGetSymbolAddress((void**)&p_wout16, g_wout16);
    cudaGetSymbolAddress((void**)&p_eo3,    g_eo3);
    cudaGetSymbolAddress((void**)&p_ua3,    g_ua3);
    cudaGetSymbolAddress((void**)&p_wa3,    g_wa3);
    cudaGetSymbolAddress((void**)&p_wih3,   g_wih3);
    cudaGetSymbolAddress((void**)&p_whh3,   g_whh3);
    cudaGetSymbolAddress((void**)&p_h3,     g_h3);
    cudaGetSymbolAddress((void**)&p_x3,     g_x3);

    // ---- prologue: conversions & splits ----
    conv_bf16<<<32000, 256>>>(W_out, p_wout16);
    split3<<<(HH * HH) / 256, 256>>>(Wa, p_wa3, HH, 0);
    split3<<<(3 * HH * 2 * HH) / 256, 256>>>(W_ih, p_wih3, 2 * HH, 0);
    split3<<<(3 * HH * HH) / 256, 256>>>(W_hh, p_whh3, HH, 0);
    split3<<<(HH * HH) / 256, 256>>>(Ua, p_ua3, HH, 0);
    split3<<<(BB * SS * HH) / 256, 256>>>(EO, p_eo3, HH, 1);   // activation side
    copy_h0<<<BB * HH / 256, 256>>>(h0);

    // keysU[B*S, H] = EO @ Ua^T + bu  (bf16x3, K'=3072)
    gemm_mma<<<dim3(HH / 128, BB * SS / 64, 1), 256>>>(
        p_eo3, p_ua3, bu, p_keysU, 3 * HH / 64, 3 * HH, 3 * HH, HH, 0);

    for (int t = 0; t < TT; t++) {
        // q partials = h3 @ Wa3^T  (K'=3072, splitK=4)
        gemm_mma<<<dim3(HH / 128, 1, 4), 256>>>(
            p_h3, p_wa3, nullptr, p_qpart, 12, 3 * HH, 3 * HH, HH, (long)BB * HH);

        // gh partials = h3 @ Whh3^T (K'=3072, splitK=4) — independent of attn
        gemm_mma<<<dim3(3 * HH / 128, 1, 4), 256>>>(
            p_h3, p_whh3, nullptr, p_ghpart, 12, 3 * HH, 3 * HH, 3 * HH,
            (long)BB * 3 * HH);

        attn_fused<<<BB, 256>>>(EO, Va, bvp, ba, emb, target, out_attn, t);

        // gi partials = x3 @ Wih3^T (K'=6144, splitK=4)
        gemm_mma<<<dim3(3 * HH / 128, 1, 4), 256>>>(
            p_x3, p_wih3, nullptr, p_gipart, 24, 6 * HH, 6 * HH, 3 * HH,
            (long)BB * 3 * HH);

        gru_step<<<BB, 256>>>(b_ih, b_hh);

        // logits = h_hi @ W_out^T + b_out (plain bf16, K=1024 via lda=3072)
        gemm_mma<<<dim3(VV / 128, 1, 1), 256>>>(
            p_h3, p_wout16, b_out, p_logits, HH / 64, 3 * HH, HH, VV, 0);

        logsoftmax_step<<<BB, 512>>>(out_dec, t);
    }

    write_hidden<<<BB * HH / 256, 256>>>(out_hid);
}

// round 8
// speedup vs baseline: 1.2498x; 1.2498x over previous
#include <cuda_runtime.h>
#include <cuda_bf16.h>
#include <math.h>

#define BB 64
#define SS 64
#define HH 1024
#define TT 40
#define VV 32000

#define LOGITS_BLKS (VV / 128)          // 250
#define QGH_BLKS    (4 * HH / 128)      // 32

// ---------------- scratch (device globals; no allocation allowed) ----------
__device__ float g_keysU[BB * SS * HH];                  // 16.8 MB fp32
__device__ float g_h[BB * HH];
__device__ float g_logits[BB * VV];                      // 8.2 MB
__device__ float g_qgh[BB * 4 * HH];                     // [q(1024) | gh(3072)]
__device__ float g_gipart[4][BB * 3 * HH];
__device__ __nv_bfloat16 g_wout16[(long)VV * HH];        // 65.5 MB
__device__ __nv_bfloat16 g_eo3[(long)BB * SS * 3 * HH];  // [hi,hi,lo] 25 MB
__device__ __nv_bfloat16 g_ua3[(long)HH * 3 * HH];       // [hi,lo,hi] 6 MB
__device__ __nv_bfloat16 g_wqh3[(long)4 * HH * 3 * HH];  // [Wa;Whh] x3, 25 MB
__device__ __nv_bfloat16 g_wih3[(long)3 * HH * 6 * HH];  // W_ih x3, 37.7 MB
__device__ __nv_bfloat16 g_h3[BB * 3 * HH];              // [hi | hi | lo]
__device__ __nv_bfloat16 g_x3[BB * 6 * HH];              // [xhi | xhi | xlo]

// ---------------------------------------------------------------------------
// helpers
// ---------------------------------------------------------------------------
__device__ __forceinline__ float fast_tanh(float x) {
    float y;
    asm("tanh.approx.f32 %0, %1;" : "=f"(y) : "f"(x));
    return y;
}
__device__ __forceinline__ unsigned sptr(const void* p) {
    return (unsigned)__cvta_generic_to_shared(p);
}
__device__ __forceinline__ void cpa16(unsigned dst, const void* src) {
    asm volatile("cp.async.cg.shared.global [%0], [%1], 16;" :: "r"(dst), "l"(src));
}
__device__ __forceinline__ void ldm4(unsigned* r, unsigned addr) {
    asm volatile("ldmatrix.sync.aligned.m8n8.x4.shared.b16 {%0,%1,%2,%3}, [%4];"
                 : "=r"(r[0]), "=r"(r[1]), "=r"(r[2]), "=r"(r[3]) : "r"(addr));
}
__device__ __forceinline__ void mma_bf16(float* d, const unsigned* a,
                                         unsigned b0, unsigned b1) {
    asm volatile(
        "mma.sync.aligned.m16n8k16.row.col.f32.bf16.bf16.f32 "
        "{%0,%1,%2,%3}, {%4,%5,%6,%7}, {%8,%9}, {%0,%1,%2,%3};"
        : "+f"(d[0]), "+f"(d[1]), "+f"(d[2]), "+f"(d[3])
        : "r"(a[0]), "r"(a[1]), "r"(a[2]), "r"(a[3]), "r"(b0), "r"(b1));
}

// ---------------------------------------------------------------------------
// Shared GEMM body: C[64, n0:n0+128] (+ bias) = A[64 rows, K'] @ B^T
// cp.async double-buffered, xor-swizzled smem, m16n8k16 HMMA, 8 warps.
// ---------------------------------------------------------------------------
__device__ __forceinline__ void gemm_body(
    const __nv_bfloat16* __restrict__ A, const __nv_bfloat16* __restrict__ Bw,
    const float* __restrict__ bias, float* __restrict__ C,
    int kcBegin, int kcPer, int lda, int ldb, int ldc,
    int m0, int n0, unsigned sb0)
{
    const int tid = threadIdx.x;
    const int wid = tid >> 5, lane = tid & 31;
    const int warp_m = wid >> 2;
    const int warp_n = wid & 3;

    float acc[2][4][4];
#pragma unroll
    for (int a = 0; a < 2; a++)
#pragma unroll
        for (int b = 0; b < 4; b++)
#pragma unroll
            for (int c = 0; c < 4; c++) acc[a][b][c] = 0.f;

    auto stage = [&](unsigned sbase, int kc) {
#pragma unroll
        for (int i = 0; i < 6; i++) {
            int idx = tid + i * 256;
            if (idx < 512) {
                int r = idx >> 3, c = idx & 7;
                unsigned dst = sbase + (unsigned)(((r << 3) + (c ^ (r & 7))) << 4);
                cpa16(dst, A + (long)(m0 + r) * lda + kc * 64 + c * 8);
            } else {
                int j = idx - 512;
                int r = j >> 3, c = j & 7;
                unsigned dst = sbase + 8192u + (unsigned)(((r << 3) + (c ^ (r & 7))) << 4);
                cpa16(dst, Bw + (long)(n0 + r) * ldb + kc * 64 + c * 8);
            }
        }
    };

    stage(sb0, kcBegin);
    asm volatile("cp.async.commit_group;");

    for (int i = 0; i < kcPer; i++) {
        if (i + 1 < kcPer) stage(sb0 + ((i + 1) & 1) * 24576u, kcBegin + i + 1);
        asm volatile("cp.async.commit_group;");
        asm volatile("cp.async.wait_group 1;");
        __syncthreads();

        const unsigned bA = sb0 + (i & 1) * 24576u;
        const unsigned bB = bA + 8192u;

#pragma unroll
        for (int kk = 0; kk < 4; kk++) {
            unsigned afr[2][4], bfr[2][4];
#pragma unroll
            for (int mt = 0; mt < 2; mt++) {
                int r = warp_m * 32 + mt * 16 + (lane & 15);
                int c = 2 * kk + (lane >> 4);
                ldm4(afr[mt], bA + (unsigned)(((r << 3) + (c ^ (r & 7))) << 4));
            }
#pragma unroll
            for (int np = 0; np < 2; np++) {
                int r = warp_n * 32 + np * 16 + ((lane >> 4) << 3) + (lane & 7);
                int c = 2 * kk + ((lane >> 3) & 1);
                ldm4(bfr[np], bB + (unsigned)(((r << 3) + (c ^ (r & 7))) << 4));
            }
#pragma unroll
            for (int mt = 0; mt < 2; mt++)
#pragma unroll
                for (int nt = 0; nt < 4; nt++)
                    mma_bf16(acc[mt][nt], afr[mt],
                             bfr[nt >> 1][(nt & 1) * 2], bfr[nt >> 1][(nt & 1) * 2 + 1]);
        }
        __syncthreads();
    }

#pragma unroll
    for (int mt = 0; mt < 2; mt++) {
        int row = m0 + warp_m * 32 + mt * 16 + (lane >> 2);
#pragma unroll
        for (int nt = 0; nt < 4; nt++) {
            int col = n0 + warp_n * 32 + nt * 8 + ((lane & 3) << 1);
            float* cp = C + (long)row * ldc + col;
            float b0 = 0.f, b1 = 0.f;
            if (bias) { b0 = bias[col]; b1 = bias[col + 1]; }
            float2 v0 = {acc[mt][nt][0] + b0, acc[mt][nt][1] + b1};
            float2 v1 = {acc[mt][nt][2] + b0, acc[mt][nt][3] + b1};
            *(float2*)cp = v0;
            *(float2*)(cp + (long)8 * ldc) = v1;
        }
    }
}

// Generic wrapper (keysU one-time GEMM; gi per-step GEMM with splitK)
__global__ void gemm_mma(const __nv_bfloat16* __restrict__ A,
                         const __nv_bfloat16* __restrict__ Bw,
                         const float* __restrict__ bias,
                         float* __restrict__ C,
                         int kcPer, int lda, int ldb, int N, long strideZ)
{
    __shared__ __align__(1024) unsigned char smem_raw[49152];
    gemm_body(A, Bw, bias, C + (long)blockIdx.z * strideZ,
              blockIdx.z * kcPer, kcPer, lda, ldb, N,
              blockIdx.y * 64, blockIdx.x * 128, sptr(smem_raw));
}

// ---------------------------------------------------------------------------
// MEGA GEMM: from g_h3 computes logits (mode&1) and q|gh (mode&2) in one launch.
//  blocks [0,250):  logits = h_hi @ W_out^T + b_out       (K=1024, hi slice)
//  blocks [250,282): qgh   = h3 @ [Wa;Whh]3^T             (x3, K'=3072)
// ---------------------------------------------------------------------------
__global__ void mega_gemm(const float* __restrict__ b_out, int mode)
{
    __shared__ __align__(1024) unsigned char smem_raw[49152];
    const int bx = blockIdx.x;
    if (bx < LOGITS_BLKS) {
        if (!(mode & 1)) return;
        gemm_body(g_h3, g_wout16, b_out, g_logits,
                  0, 16, 3 * HH, HH, VV, 0, bx * 128, sptr(smem_raw));
    } else {
        if (!(mode & 2)) return;
        gemm_body(g_h3, g_wqh3, nullptr, g_qgh,
                  0, 48, 3 * HH, 3 * HH, 4 * HH, 0, (bx - LOGITS_BLKS) * 128,
                  sptr(smem_raw));
    }
}

// ---------------------------------------------------------------------------
// Conversions / prologue kernels
// ---------------------------------------------------------------------------
__global__ void conv_bf16(const float* __restrict__ s, __nv_bfloat16* __restrict__ d)
{
    long i = ((long)blockIdx.x * 256 + threadIdx.x) * 4;
    float4 v = *(const float4*)(s + i);
    __nv_bfloat162* dp = (__nv_bfloat162*)(d + i);
    dp[0] = __floats2bfloat162_rn(v.x, v.y);
    dp[1] = __floats2bfloat162_rn(v.z, v.w);
}

// bf16x3 split. isA=1: [hi,hi,lo] (activation); isA=0: [hi,lo,hi] (weight)
__global__ void split3_2d(const float* __restrict__ in,
                          __nv_bfloat16* __restrict__ out, int K, int isA)
{
    const int r = blockIdx.y;
    const int k = blockIdx.x * 256 + threadIdx.x;
    float v = in[(long)r * K + k];
    __nv_bfloat16 hi = __float2bfloat16(v);
    __nv_bfloat16 lo = __float2bfloat16(v - __bfloat162float(hi));
    long o = (long)r * 3 * K + k;
    out[o] = hi;
    out[o + K] = isA ? hi : lo;
    out[o + 2 * K] = isA ? lo : hi;
}

__global__ void copy_h0(const float* __restrict__ h0)
{
    int i = blockIdx.x * 256 + threadIdx.x;
    float v = h0[i];
    g_h[i] = v;
    int r = i >> 10, k = i & 1023;
    __nv_bfloat16 hi = __float2bfloat16(v);
    __nv_bfloat16 lo = __float2bfloat16(v - __bfloat162float(hi));
    g_h3[r * 3072 + k] = hi;
    g_h3[r * 3072 + 1024 + k] = hi;
    g_h3[r * 3072 + 2048 + k] = lo;
}

__global__ void write_hidden(float* __restrict__ out_hid)
{
    int i = blockIdx.x * 256 + threadIdx.x;
    out_hid[i] = g_h[i];
}

// ---------------------------------------------------------------------------
// attn (blocks 0..63, mode&1) || log-softmax of step t-1 (blocks 64..127, mode&2)
// 512 threads.
// ---------------------------------------------------------------------------
__global__ void attn_lsm(const float* __restrict__ EO,
                         const float* __restrict__ Va,
                         const float* __restrict__ bv,
                         const float* __restrict__ ba,
                         const float* __restrict__ emb,
                         const int* __restrict__ target,
                         float* __restrict__ out_attn,
                         float* __restrict__ out_dec,
                         int t, int mode)
{
    __shared__ float qs[HH];
    __shared__ float vs[HH];
    __shared__ float sc[SS];
    __shared__ float w[SS];
    __shared__ float red[512];
    const int bx = blockIdx.x;
    const int tid = threadIdx.x;

    if (bx < 64) {
        if (!(mode & 1)) return;
        const int b = bx;
        const int warp = tid >> 5, lane = tid & 31;

        for (int i = tid; i < HH; i += 512) {
            qs[i] = g_qgh[b * 4 * HH + i] + ba[i];
            vs[i] = Va[i];
        }
        __syncthreads();

        for (int s = warp; s < SS; s += 16) {
            const float* kp = &g_keysU[((long)(b * SS + s)) * HH];
            float sum = 0.f;
            for (int h = lane; h < HH; h += 32)
                sum += fast_tanh(qs[h] + kp[h]) * vs[h];
#pragma unroll
            for (int o = 16; o; o >>= 1) sum += __shfl_xor_sync(~0u, sum, o);
            if (!lane) sc[s] = sum + bv[0];
        }
        __syncthreads();

        if (warp == 0) {
            float v0 = sc[lane], v1 = sc[lane + 32];
            float mx = fmaxf(v0, v1);
#pragma unroll
            for (int o = 16; o; o >>= 1) mx = fmaxf(mx, __shfl_xor_sync(~0u, mx, o));
            float e0 = expf(v0 - mx), e1 = expf(v1 - mx);
            float sm = e0 + e1;
#pragma unroll
            for (int o = 16; o; o >>= 1) sm += __shfl_xor_sync(~0u, sm, o);
            float inv = 1.f / sm;
            w[lane] = e0 * inv;
            w[lane + 32] = e1 * inv;
            out_attn[((long)(b * TT + t)) * SS + lane] = e0 * inv;
            out_attn[((long)(b * TT + t)) * SS + lane + 32] = e1 * inv;
        }
        __syncthreads();

        const int tok = (t == 0) ? 0 : target[b * TT + t - 1];  // SOS_INDEX = 0
        __nv_bfloat16* xr = &g_x3[b * 6 * HH];

        for (int h = tid; h < HH; h += 512) {
            float acc = 0.f;
            const float* ep = &EO[(long)b * SS * HH + h];
#pragma unroll 8
            for (int s = 0; s < SS; s++) acc += w[s] * ep[(long)s * HH];
            __nv_bfloat16 chi = __float2bfloat16(acc);
            __nv_bfloat16 clo = __float2bfloat16(acc - __bfloat162float(chi));
            xr[1024 + h] = chi;          // x hi copy 1, ctx half
            xr[2048 + 1024 + h] = chi;   // x hi copy 2, ctx half
            xr[4096 + 1024 + h] = clo;   // x lo,        ctx half
            float e = emb[(long)tok * HH + h];
            __nv_bfloat16 ehi = __float2bfloat16(e);
            __nv_bfloat16 elo = __float2bfloat16(e - __bfloat162float(ehi));
            xr[h] = ehi;                 // x hi copy 1, emb half
            xr[2048 + h] = ehi;          // x hi copy 2, emb half
            xr[4096 + h] = elo;          // x lo,        emb half
        }
    } else {
        if (!(mode & 2)) return;
        const int b = bx - 64;
        const int tp = t - 1;
        const float* lg = &g_logits[(long)b * VV];

        float mx = -1e30f;
        for (int v = tid; v < VV; v += 512) mx = fmaxf(mx, lg[v]);
        red[tid] = mx; __syncthreads();
        for (int s = 256; s; s >>= 1) {
            if (tid < s) red[tid] = fmaxf(red[tid], red[tid + s]);
            __syncthreads();
        }
        mx = red[0];
        __syncthreads();

        float sum = 0.f;
        for (int v = tid; v < VV; v += 512) sum += expf(lg[v] - mx);
        red[tid] = sum; __syncthreads();
        for (int s = 256; s; s >>= 1) {
            if (tid < s) red[tid] += red[tid + s];
            __syncthreads();
        }
        const float lse = mx + logf(red[0]);

        float* op = &out_dec[((long)(b * TT + tp)) * VV];
        for (int v = tid; v < VV; v += 512) op[v] = lg[v] - lse;
    }
}

// ---------------------------------------------------------------------------
// GRU: sums 4 gi partials + gh (from g_qgh) + biases; updates g_h / g_h3
// ---------------------------------------------------------------------------
__global__ void gru_step(const float* __restrict__ b_ih, const float* __restrict__ b_hh)
{
    const int b = blockIdx.x;
    for (int j = threadIdx.x; j < HH; j += 256) {
        const int base = b * 3 * HH;
        float ir = 0, iz = 0, in = 0;
#pragma unroll
        for (int z = 0; z < 4; z++) {
            ir += g_gipart[z][base + j];
            iz += g_gipart[z][base + HH + j];
            in += g_gipart[z][base + 2 * HH + j];
        }
        const float* qg = &g_qgh[b * 4 * HH];
        float hr = qg[HH + j];
        float hz = qg[2 * HH + j];
        float hn = qg[3 * HH + j];
        ir += b_ih[j]; iz += b_ih[HH + j]; in += b_ih[2 * HH + j];
        hr += b_hh[j]; hz += b_hh[HH + j]; hn += b_hh[2 * HH + j];
        float r = 1.f / (1.f + expf(-(ir + hr)));
        float z = 1.f / (1.f + expf(-(iz + hz)));
        float n = tanhf(in + r * hn);
        float ho = g_h[b * HH + j];
        float out = (1.f - z) * n + z * ho;
        g_h[b * HH + j] = out;
        __nv_bfloat16 hi = __float2bfloat16(out);
        __nv_bfloat16 lo = __float2bfloat16(out - __bfloat162float(hi));
        g_h3[b * 3072 + j] = hi;
        g_h3[b * 3072 + 1024 + j] = hi;
        g_h3[b * 3072 + 2048 + j] = lo;
    }
}

// ---------------------------------------------------------------------------
extern "C" void kernel_launch(void* const* d_in, const int* in_sizes, int n_in,
                              void* d_out, int out_size)
{
    const float* EO     = (const float*)d_in[0];   // [B,S,H]
    const float* h0     = (const float*)d_in[1];   // [B,H]
    const int*   target = (const int*)  d_in[2];   // [B,T]
    const float* emb    = (const float*)d_in[3];   // [V,H]
    const float* Wa     = (const float*)d_in[4];   // [H,H]
    const float* ba     = (const float*)d_in[5];
    const float* Ua     = (const float*)d_in[6];   // [H,H]
    const float* bu     = (const float*)d_in[7];
    const float* Va     = (const float*)d_in[8];   // [1,H]
    const float* bvp    = (const float*)d_in[9];
    const float* W_ih   = (const float*)d_in[10];  // [3H,2H]
    const float* W_hh   = (const float*)d_in[11];  // [3H,H]
    const float* b_ih   = (const float*)d_in[12];
    const float* b_hh   = (const float*)d_in[13];
    const float* W_out  = (const float*)d_in[14];  // [V,H]
    const float* b_out  = (const float*)d_in[15];

    float* out      = (float*)d_out;
    float* out_dec  = out;                          // [B,T,V]
    float* out_hid  = out + (long)BB * TT * VV;     // [1,B,H]
    float* out_attn = out_hid + (long)BB * HH;      // [B,T,S]

    float *p_keysU, *p_gipart;
    __nv_bfloat16 *p_wout16, *p_eo3, *p_ua3, *p_wqh3, *p_wih3, *p_x3;
    cudaGetSymbolAddress((void**)&p_keysU,  g_keysU);
    cudaGetSymbolAddress((void**)&p_gipart, g_gipart);
    cudaGetSymbolAddress((void**)&p_wout16, g_wout16);
    cudaGetSymbolAddress((void**)&p_eo3,    g_eo3);
    cudaGetSymbolAddress((void**)&p_ua3,    g_ua3);
    cudaGetSymbolAddress((void**)&p_wqh3,   g_wqh3);
    cudaGetSymbolAddress((void**)&p_wih3,   g_wih3);
    cudaGetSymbolAddress((void**)&p_x3,     g_x3);

    // ---- prologue ----
    conv_bf16<<<32000, 256>>>(W_out, p_wout16);
    split3_2d<<<dim3(4, 1024), 256>>>(Wa, p_wqh3, HH, 0);                       // q rows
    split3_2d<<<dim3(4, 3072), 256>>>(W_hh, p_wqh3 + (long)HH * 3 * HH, HH, 0); // gh rows
    split3_2d<<<dim3(8, 3072), 256>>>(W_ih, p_wih3, 2 * HH, 0);
    split3_2d<<<dim3(4, 1024), 256>>>(Ua, p_ua3, HH, 0);
    split3_2d<<<dim3(4, 4096), 256>>>(EO, p_eo3, HH, 1);
    copy_h0<<<BB * HH / 256, 256>>>(h0);

    // keysU = EO @ Ua^T + bu  (bf16x3; one-time)
    gemm_mma<<<dim3(HH / 128, BB * SS / 64, 1), 256>>>(
        p_eo3, p_ua3, bu, p_keysU, 3 * HH / 64, 3 * HH, 3 * HH, HH, 0);

    for (int t = 0; t < TT; t++) {
        // logits_{t-1} (skip at t=0) + q_t,gh_t (x3) — one launch
        mega_gemm<<<LOGITS_BLKS + QGH_BLKS, 256>>>(b_out, (t > 0 ? 1 : 0) | 2);
        // attention(t) || log_softmax(t-1)
        attn_lsm<<<128, 512>>>(EO, Va, bvp, ba, emb, target, out_attn, out_dec,
                               t, 1 | (t > 0 ? 2 : 0));
        // gi partials = x3 @ Wih3^T (K'=6144, splitK=4)
        gemm_mma<<<dim3(3 * HH / 128, 1, 4), 256>>>(
            p_x3, p_wih3, nullptr, p_gipart, 24, 6 * HH, 6 * HH, 3 * HH,
            (long)BB * 3 * HH);
        gru_step<<<BB, 256>>>(b_ih, b_hh);
    }

    // tail: logits_39 + log_softmax_39
    mega_gemm<<<LOGITS_BLKS + QGH_BLKS, 256>>>(b_out, 1);
    attn_lsm<<<128, 512>>>(EO, Va, bvp, ba, emb, target, out_attn, out_dec,
                           TT, 2);

    write_hidden<<<BB * HH / 256, 256>>>(out_hid);
}

// round 9
// speedup vs baseline: 1.4866x; 1.1894x over previous
#include <cuda_runtime.h>
#include <cuda_bf16.h>
#include <math.h>

#define BB 64
#define SS 64
#define HH 1024
#define TT 40
#define VV 32000

#define LOGITS_BLKS (VV / 128)          // 250
#define QGH2_BLKS   64                  // 32 n-tiles x 2 K-slices
#define SMEM_DYN    73728               // 3 x 24576 (3-stage pipeline)
#define GI_BLOCKS   96                  // 24 n-tiles x 4 K-slices (<=148: co-resident)

// ---------------- scratch (device globals; no allocation allowed) ----------
__device__ float g_keysU[BB * SS * HH];                  // 16.8 MB fp32
__device__ float g_h[BB * HH];
__device__ float g_logits[BB * VV];                      // 8.2 MB
__device__ float g_qghp[2][BB * 4 * HH];                 // qgh split-K partials
__device__ float g_gipart[4][BB * 3 * HH];
__device__ int   g_ctr[2];                               // gi+gru spin barrier
__device__ __nv_bfloat16 g_wout16[(long)VV * HH];        // 65.5 MB
__device__ __nv_bfloat16 g_eo3[(long)BB * SS * 3 * HH];  // [hi,hi,lo] 25 MB
__device__ __nv_bfloat16 g_ua3[(long)HH * 3 * HH];       // [hi,lo,hi] 6 MB
__device__ __nv_bfloat16 g_wqh3[(long)4 * HH * 3 * HH];  // [Wa;Whh] x3, 25 MB
__device__ __nv_bfloat16 g_wih3[(long)3 * HH * 6 * HH];  // W_ih x3, 37.7 MB
__device__ __nv_bfloat16 g_h3[BB * 3 * HH];              // [hi | hi | lo]
__device__ __nv_bfloat16 g_x3[BB * 6 * HH];              // [xhi | xhi | xlo]

// ---------------------------------------------------------------------------
// helpers
// ---------------------------------------------------------------------------
__device__ __forceinline__ float fast_tanh(float x) {
    float y;
    asm("tanh.approx.f32 %0, %1;" : "=f"(y) : "f"(x));
    return y;
}
__device__ __forceinline__ unsigned sptr(const void* p) {
    return (unsigned)__cvta_generic_to_shared(p);
}
__device__ __forceinline__ void cpa16(unsigned dst, const void* src) {
    asm volatile("cp.async.cg.shared.global [%0], [%1], 16;" :: "r"(dst), "l"(src));
}
__device__ __forceinline__ void ldm4(unsigned* r, unsigned addr) {
    asm volatile("ldmatrix.sync.aligned.m8n8.x4.shared.b16 {%0,%1,%2,%3}, [%4];"
                 : "=r"(r[0]), "=r"(r[1]), "=r"(r[2]), "=r"(r[3]) : "r"(addr));
}
__device__ __forceinline__ void mma_bf16(float* d, const unsigned* a,
                                         unsigned b0, unsigned b1) {
    asm volatile(
        "mma.sync.aligned.m16n8k16.row.col.f32.bf16.bf16.f32 "
        "{%0,%1,%2,%3}, {%4,%5,%6,%7}, {%8,%9}, {%0,%1,%2,%3};"
        : "+f"(d[0]), "+f"(d[1]), "+f"(d[2]), "+f"(d[3])
        : "r"(a[0]), "r"(a[1]), "r"(a[2]), "r"(a[3]), "r"(b0), "r"(b1));
}

// ---------------------------------------------------------------------------
// Shared GEMM body: C[64, n0:n0+128] (+ bias) = A[64 rows, K'] @ B^T
// cp.async TRIPLE-buffered (wait_group 2), xor-swizzled smem, m16n8k16, 8 warps.
// ---------------------------------------------------------------------------
__device__ __forceinline__ void gemm_body(
    const __nv_bfloat16* __restrict__ A, const __nv_bfloat16* __restrict__ Bw,
    const float* __restrict__ bias, float* __restrict__ C,
    int kcBegin, int kcPer, int lda, int ldb, int ldc,
    int m0, int n0, unsigned sb0)
{
    const unsigned BUF = 24576u;
    const int tid = threadIdx.x;
    const int wid = tid >> 5, lane = tid & 31;
    const int warp_m = wid >> 2;
    const int warp_n = wid & 3;

    float acc[2][4][4];
#pragma unroll
    for (int a = 0; a < 2; a++)
#pragma unroll
        for (int b = 0; b < 4; b++)
#pragma unroll
            for (int c = 0; c < 4; c++) acc[a][b][c] = 0.f;

    auto stage = [&](unsigned sbase, int kc) {
#pragma unroll
        for (int i = 0; i < 6; i++) {
            int idx = tid + i * 256;
            if (idx < 512) {
                int r = idx >> 3, c = idx & 7;
                unsigned dst = sbase + (unsigned)(((r << 3) + (c ^ (r & 7))) << 4);
                cpa16(dst, A + (long)(m0 + r) * lda + kc * 64 + c * 8);
            } else {
                int j = idx - 512;
                int r = j >> 3, c = j & 7;
                unsigned dst = sbase + 8192u + (unsigned)(((r << 3) + (c ^ (r & 7))) << 4);
                cpa16(dst, Bw + (long)(n0 + r) * ldb + kc * 64 + c * 8);
            }
        }
    };

    stage(sb0, kcBegin);
    asm volatile("cp.async.commit_group;");
    if (kcPer > 1) stage(sb0 + BUF, kcBegin + 1);
    asm volatile("cp.async.commit_group;");

    for (int i = 0; i < kcPer; i++) {
        if (i + 2 < kcPer) stage(sb0 + (unsigned)((i + 2) % 3) * BUF, kcBegin + i + 2);
        asm volatile("cp.async.commit_group;");
        asm volatile("cp.async.wait_group 2;");
        __syncthreads();

        const unsigned bA = sb0 + (unsigned)(i % 3) * BUF;
        const unsigned bB = bA + 8192u;

#pragma unroll
        for (int kk = 0; kk < 4; kk++) {
            unsigned afr[2][4], bfr[2][4];
#pragma unroll
            for (int mt = 0; mt < 2; mt++) {
                int r = warp_m * 32 + mt * 16 + (lane & 15);
                int c = 2 * kk + (lane >> 4);
                ldm4(afr[mt], bA + (unsigned)(((r << 3) + (c ^ (r & 7))) << 4));
            }
#pragma unroll
            for (int np = 0; np < 2; np++) {
                int r = warp_n * 32 + np * 16 + ((lane >> 4) << 3) + (lane & 7);
                int c = 2 * kk + ((lane >> 3) & 1);
                ldm4(bfr[np], bB + (unsigned)(((r << 3) + (c ^ (r & 7))) << 4));
            }
#pragma unroll
            for (int mt = 0; mt < 2; mt++)
#pragma unroll
                for (int nt = 0; nt < 4; nt++)
                    mma_bf16(acc[mt][nt], afr[mt],
                             bfr[nt >> 1][(nt & 1) * 2], bfr[nt >> 1][(nt & 1) * 2 + 1]);
        }
        __syncthreads();
    }

#pragma unroll
    for (int mt = 0; mt < 2; mt++) {
        int row = m0 + warp_m * 32 + mt * 16 + (lane >> 2);
#pragma unroll
        for (int nt = 0; nt < 4; nt++) {
            int col = n0 + warp_n * 32 + nt * 8 + ((lane & 3) << 1);
            float* cp = C + (long)row * ldc + col;
            float b0 = 0.f, b1 = 0.f;
            if (bias) { b0 = bias[col]; b1 = bias[col + 1]; }
            float2 v0 = {acc[mt][nt][0] + b0, acc[mt][nt][1] + b1};
            float2 v1 = {acc[mt][nt][2] + b0, acc[mt][nt][3] + b1};
            *(float2*)cp = v0;
            *(float2*)(cp + (long)8 * ldc) = v1;
        }
    }
}

// Generic wrapper (keysU one-time GEMM)
__global__ void gemm_mma(const __nv_bfloat16* __restrict__ A,
                         const __nv_bfloat16* __restrict__ Bw,
                         const float* __restrict__ bias,
                         float* __restrict__ C,
                         int kcPer, int lda, int ldb, int N, long strideZ)
{
    extern __shared__ unsigned char smem_raw[];
    gemm_body(A, Bw, bias, C + (long)blockIdx.z * strideZ,
              blockIdx.z * kcPer, kcPer, lda, ldb, N,
              blockIdx.y * 64, blockIdx.x * 128, sptr(smem_raw));
}

// ---------------------------------------------------------------------------
// MEGA GEMM: qgh split-K partials (blocks 0..63, mode&2) + logits (64.., mode&1)
// ---------------------------------------------------------------------------
__global__ void mega_gemm(const float* __restrict__ b_out, int mode)
{
    extern __shared__ unsigned char smem_raw[];
    const int bx = blockIdx.x;
    if (bx < QGH2_BLKS) {
        if (!(mode & 2)) return;
        const int z = bx >> 5;          // K-slice 0/1
        const int n0 = (bx & 31) * 128;
        gemm_body(g_h3, g_wqh3, nullptr, g_qghp[z],
                  z * 24, 24, 3 * HH, 3 * HH, 4 * HH, 0, n0, sptr(smem_raw));
    } else {
        if (!(mode & 1)) return;
        gemm_body(g_h3, g_wout16, b_out, g_logits,
                  0, 16, 3 * HH, HH, VV, 0, (bx - QGH2_BLKS) * 128, sptr(smem_raw));
    }
}

// ---------------------------------------------------------------------------
// gi GEMM + GRU fused. grid (24,1,4) = 96 blocks (co-resident on 148 SMs).
// After the split-K partial store, blocks arrive on a parity counter, spin
// until all 96 arrived, then cooperatively run the GRU pointwise update.
// ---------------------------------------------------------------------------
__global__ void gi_gru(const float* __restrict__ b_ih,
                       const float* __restrict__ b_hh, int t)
{
    extern __shared__ unsigned char smem_raw[];
    const int tid = threadIdx.x;
    const int par = t & 1;
    if (tid == 0 && blockIdx.x == 0 && blockIdx.z == 0)
        g_ctr[1 - par] = 0;             // reset other slot for next step

    gemm_body(g_x3, g_wih3, nullptr, g_gipart[blockIdx.z],
              blockIdx.z * 24, 24, 6 * HH, 6 * HH, 3 * HH,
              0, blockIdx.x * 128, sptr(smem_raw));

    // arrive + spin (all 96 blocks co-resident -> deadlock-free)
    __threadfence();
    __syncthreads();
    if (tid == 0) {
        atomicAdd(&g_ctr[par], 1);
        while (*((volatile int*)&g_ctr[par]) < GI_BLOCKS) __nanosleep(64);
    }
    __syncthreads();
    __threadfence();

    // GRU: each block handles a strided slice of the 64x1024 elements
    const int bid = blockIdx.x + 24 * blockIdx.z;
    for (int idx = bid * 256 + tid; idx < BB * HH; idx += GI_BLOCKS * 256) {
        const int b = idx >> 10, j = idx & 1023;
        const int base = b * 3 * HH;
        float ir = 0, iz = 0, in = 0;
#pragma unroll
        for (int z = 0; z < 4; z++) {
            ir += g_gipart[z][base + j];
            iz += g_gipart[z][base + HH + j];
            in += g_gipart[z][base + 2 * HH + j];
        }
        const float* q0 = &g_qghp[0][b * 4 * HH];
        const float* q1 = &g_qghp[1][b * 4 * HH];
        float hr = q0[HH + j] + q1[HH + j];
        float hz = q0[2 * HH + j] + q1[2 * HH + j];
        float hn = q0[3 * HH + j] + q1[3 * HH + j];
        ir += b_ih[j]; iz += b_ih[HH + j]; in += b_ih[2 * HH + j];
        hr += b_hh[j]; hz += b_hh[HH + j]; hn += b_hh[2 * HH + j];
        float r = 1.f / (1.f + expf(-(ir + hr)));
        float z = 1.f / (1.f + expf(-(iz + hz)));
        float n = tanhf(in + r * hn);
        float ho = g_h[idx];
        float out = (1.f - z) * n + z * ho;
        g_h[idx] = out;
        __nv_bfloat16 hi = __float2bfloat16(out);
        __nv_bfloat16 lo = __float2bfloat16(out - __bfloat162float(hi));
        g_h3[b * 3072 + j] = hi;
        g_h3[b * 3072 + 1024 + j] = hi;
        g_h3[b * 3072 + 2048 + j] = lo;
    }
}

// ---------------------------------------------------------------------------
// Conversions / prologue kernels
// ---------------------------------------------------------------------------
__global__ void conv_bf16(const float* __restrict__ s, __nv_bfloat16* __restrict__ d)
{
    long i = ((long)blockIdx.x * 256 + threadIdx.x) * 4;
    float4 v = *(const float4*)(s + i);
    __nv_bfloat162* dp = (__nv_bfloat162*)(d + i);
    dp[0] = __floats2bfloat162_rn(v.x, v.y);
    dp[1] = __floats2bfloat162_rn(v.z, v.w);
}

// bf16x3 split. isA=1: [hi,hi,lo] (activation); isA=0: [hi,lo,hi] (weight)
__global__ void split3_2d(const float* __restrict__ in,
                          __nv_bfloat16* __restrict__ out, int K, int isA)
{
    const int r = blockIdx.y;
    const int k = blockIdx.x * 256 + threadIdx.x;
    float v = in[(long)r * K + k];
    __nv_bfloat16 hi = __float2bfloat16(v);
    __nv_bfloat16 lo = __float2bfloat16(v - __bfloat162float(hi));
    long o = (long)r * 3 * K + k;
    out[o] = hi;
    out[o + K] = isA ? hi : lo;
    out[o + 2 * K] = isA ? lo : hi;
}

__global__ void copy_h0(const float* __restrict__ h0)
{
    int i = blockIdx.x * 256 + threadIdx.x;
    float v = h0[i];
    g_h[i] = v;
    int r = i >> 10, k = i & 1023;
    __nv_bfloat16 hi = __float2bfloat16(v);
    __nv_bfloat16 lo = __float2bfloat16(v - __bfloat162float(hi));
    g_h3[r * 3072 + k] = hi;
    g_h3[r * 3072 + 1024 + k] = hi;
    g_h3[r * 3072 + 2048 + k] = lo;
    if (i < 2) g_ctr[i] = 0;            // barrier counters start clean
}

__global__ void write_hidden(float* __restrict__ out_hid)
{
    int i = blockIdx.x * 256 + threadIdx.x;
    out_hid[i] = g_h[i];
}

// ---------------------------------------------------------------------------
// attn (blocks 0..63, mode&1) || log-softmax of step t-1 (blocks 64..127, mode&2)
// 512 threads.
// ---------------------------------------------------------------------------
__global__ void attn_lsm(const float* __restrict__ EO,
                         const float* __restrict__ Va,
                         const float* __restrict__ bv,
                         const float* __restrict__ ba,
                         const float* __restrict__ emb,
                         const int* __restrict__ target,
                         float* __restrict__ out_attn,
                         float* __restrict__ out_dec,
                         int t, int mode)
{
    __shared__ float qs[HH];
    __shared__ float vs[HH];
    __shared__ float sc[SS];
    __shared__ float w[SS];
    __shared__ float red[512];
    const int bx = blockIdx.x;
    const int tid = threadIdx.x;

    if (bx < 64) {
        if (!(mode & 1)) return;
        const int b = bx;
        const int warp = tid >> 5, lane = tid & 31;

        for (int i = tid; i < HH; i += 512) {
            qs[i] = g_qghp[0][b * 4 * HH + i] + g_qghp[1][b * 4 * HH + i] + ba[i];
            vs[i] = Va[i];
        }
        __syncthreads();

        for (int s = warp; s < SS; s += 16) {
            const float* kp = &g_keysU[((long)(b * SS + s)) * HH];
            float sum = 0.f;
            for (int h = lane; h < HH; h += 32)
                sum += fast_tanh(qs[h] + kp[h]) * vs[h];
#pragma unroll
            for (int o = 16; o; o >>= 1) sum += __shfl_xor_sync(~0u, sum, o);
            if (!lane) sc[s] = sum + bv[0];
        }
        __syncthreads();

        if (warp == 0) {
            float v0 = sc[lane], v1 = sc[lane + 32];
            float mx = fmaxf(v0, v1);
#pragma unroll
            for (int o = 16; o; o >>= 1) mx = fmaxf(mx, __shfl_xor_sync(~0u, mx, o));
            float e0 = expf(v0 - mx), e1 = expf(v1 - mx);
            float sm = e0 + e1;
#pragma unroll
            for (int o = 16; o; o >>= 1) sm += __shfl_xor_sync(~0u, sm, o);
            float inv = 1.f / sm;
            w[lane] = e0 * inv;
            w[lane + 32] = e1 * inv;
            out_attn[((long)(b * TT + t)) * SS + lane] = e0 * inv;
            out_attn[((long)(b * TT + t)) * SS + lane + 32] = e1 * inv;
        }
        __syncthreads();

        const int tok = (t == 0) ? 0 : target[b * TT + t - 1];  // SOS_INDEX = 0
        __nv_bfloat16* xr = &g_x3[b * 6 * HH];

        for (int h = tid; h < HH; h += 512) {
            float acc = 0.f;
            const float* ep = &EO[(long)b * SS * HH + h];
#pragma unroll 8
            for (int s = 0; s < SS; s++) acc += w[s] * ep[(long)s * HH];
            __nv_bfloat16 chi = __float2bfloat16(acc);
            __nv_bfloat16 clo = __float2bfloat16(acc - __bfloat162float(chi));
            xr[1024 + h] = chi;
            xr[2048 + 1024 + h] = chi;
            xr[4096 + 1024 + h] = clo;
            float e = emb[(long)tok * HH + h];
            __nv_bfloat16 ehi = __float2bfloat16(e);
            __nv_bfloat16 elo = __float2bfloat16(e - __bfloat162float(ehi));
            xr[h] = ehi;
            xr[2048 + h] = ehi;
            xr[4096 + h] = elo;
        }
    } else {
        if (!(mode & 2)) return;
        const int b = bx - 64;
        const int tp = t - 1;
        const float* lg = &g_logits[(long)b * VV];

        float mx = -1e30f;
        for (int v = tid; v < VV; v += 512) mx = fmaxf(mx, lg[v]);
        red[tid] = mx; __syncthreads();
        for (int s = 256; s; s >>= 1) {
            if (tid < s) red[tid] = fmaxf(red[tid], red[tid + s]);
            __syncthreads();
        }
        mx = red[0];
        __syncthreads();

        float sum = 0.f;
        for (int v = tid; v < VV; v += 512) sum += expf(lg[v] - mx);
        red[tid] = sum; __syncthreads();
        for (int s = 256; s; s >>= 1) {
            if (tid < s) red[tid] += red[tid + s];
            __syncthreads();
        }
        const float lse = mx + logf(red[0]);

        float* op = &out_dec[((long)(b * TT + tp)) * VV];
        for (int v = tid; v < VV; v += 512) op[v] = lg[v] - lse;
    }
}

// ---------------------------------------------------------------------------
extern "C" void kernel_launch(void* const* d_in, const int* in_sizes, int n_in,
                              void* d_out, int out_size)
{
    const float* EO     = (const float*)d_in[0];   // [B,S,H]
    const float* h0     = (const float*)d_in[1];   // [B,H]
    const int*   target = (const int*)  d_in[2];   // [B,T]
    const float* emb    = (const float*)d_in[3];   // [V,H]
    const float* Wa     = (const float*)d_in[4];   // [H,H]
    const float* ba     = (const float*)d_in[5];
    const float* Ua     = (const float*)d_in[6];   // [H,H]
    const float* bu     = (const float*)d_in[7];
    const float* Va     = (const float*)d_in[8];   // [1,H]
    const float* bvp    = (const float*)d_in[9];
    const float* W_ih   = (const float*)d_in[10];  // [3H,2H]
    const float* W_hh   = (const float*)d_in[11];  // [3H,H]
    const float* b_ih   = (const float*)d_in[12];
    const float* b_hh   = (const float*)d_in[13];
    const float* W_out  = (const float*)d_in[14];  // [V,H]
    const float* b_out  = (const float*)d_in[15];

    float* out      = (float*)d_out;
    float* out_dec  = out;                          // [B,T,V]
    float* out_hid  = out + (long)BB * TT * VV;     // [1,B,H]
    float* out_attn = out_hid + (long)BB * HH;      // [B,T,S]

    float *p_keysU;
    __nv_bfloat16 *p_wout16, *p_eo3, *p_ua3, *p_wqh3, *p_wih3;
    cudaGetSymbolAddress((void**)&p_keysU,  g_keysU);
    cudaGetSymbolAddress((void**)&p_wout16, g_wout16);
    cudaGetSymbolAddress((void**)&p_eo3,    g_eo3);
    cudaGetSymbolAddress((void**)&p_ua3,    g_ua3);
    cudaGetSymbolAddress((void**)&p_wqh3,   g_wqh3);
    cudaGetSymbolAddress((void**)&p_wih3,   g_wih3);

    // dynamic-smem opt-in (idempotent; host-side, not captured)
    cudaFuncSetAttribute(gemm_mma,  cudaFuncAttributeMaxDynamicSharedMemorySize, SMEM_DYN);
    cudaFuncSetAttribute(mega_gemm, cudaFuncAttributeMaxDynamicSharedMemorySize, SMEM_DYN);
    cudaFuncSetAttribute(gi_gru,    cudaFuncAttributeMaxDynamicSharedMemorySize, SMEM_DYN);

    // ---- prologue ----
    conv_bf16<<<32000, 256>>>(W_out, p_wout16);
    split3_2d<<<dim3(4, 1024), 256>>>(Wa, p_wqh3, HH, 0);                       // q rows
    split3_2d<<<dim3(4, 3072), 256>>>(W_hh, p_wqh3 + (long)HH * 3 * HH, HH, 0); // gh rows
    split3_2d<<<dim3(8, 3072), 256>>>(W_ih, p_wih3, 2 * HH, 0);
    split3_2d<<<dim3(4, 1024), 256>>>(Ua, p_ua3, HH, 0);
    split3_2d<<<dim3(4, 4096), 256>>>(EO, p_eo3, HH, 1);
    copy_h0<<<BB * HH / 256, 256>>>(h0);

    // keysU = EO @ Ua^T + bu  (bf16x3; one-time)
    gemm_mma<<<dim3(HH / 128, BB * SS / 64, 1), 256, SMEM_DYN>>>(
        p_eo3, p_ua3, bu, p_keysU, 3 * HH / 64, 3 * HH, 3 * HH, HH, 0);

    for (int t = 0; t < TT; t++) {
        // qgh partials (2x24 chunks) + logits_{t-1} (skip at t=0) — one launch
        mega_gemm<<<QGH2_BLKS + LOGITS_BLKS, 256, SMEM_DYN>>>(
            b_out, (t > 0 ? 1 : 0) | 2);
        // attention(t) || log_softmax(t-1)
        attn_lsm<<<128, 512>>>(EO, Va, bvp, ba, emb, target, out_attn, out_dec,
                               t, 1 | (t > 0 ? 2 : 0));
        // gi partials + GRU, fused with device-side barrier
        gi_gru<<<dim3(24, 1, 4), 256, SMEM_DYN>>>(b_ih, b_hh, t);
    }

    // tail: logits_39 + log_softmax_39
    mega_gemm<<<QGH2_BLKS + LOGITS_BLKS, 256, SMEM_DYN>>>(b_out, 1);
    attn_lsm<<<128, 512>>>(EO, Va, bvp, ba, emb, target, out_attn, out_dec,
                           TT, 2);

    write_hidden<<<BB * HH / 256, 256>>>(out_hid);
}